// round 2
// baseline (speedup 1.0000x reference)
#include <cuda_runtime.h>
#include <math.h>

// Problem constants (fixed shapes: B=2,S=2048,H=2048,E=8,A=64,NS=16384)
#define T_TOK   4096
#define H_DIM   2048
#define E_NUM   8
#define A_NUM   64
#define NS_NUM  16384
#define H_SHIFT 11
#define H_MASK  2047

// ---------------- device scratch (no allocations allowed) ----------------
__device__ float          g_weighted[E_NUM * NS_NUM];  // softmax(eaw)@atoms * sigmoid(imp)
__device__ float          g_wsrt[E_NUM * NS_NUM];      // weighted, permuted into CSR order
__device__ unsigned short g_colsrt[NS_NUM];            // col per CSR entry
__device__ int            g_counts[H_DIM];
__device__ int            g_rowptr[H_DIM + 1];
__device__ int            g_offsets[H_DIM];
__device__ int            g_e0[T_TOK];
__device__ int            g_e1[T_TOK];
__device__ float          g_rw0[T_TOK];
__device__ float          g_rw1[T_TOK];

// ---------------- tiny setup kernels ----------------
__global__ void zero_counts_kernel() {
    int i = blockIdx.x * blockDim.x + threadIdx.x;
    if (i < H_DIM) g_counts[i] = 0;
}

__global__ void hist_kernel(const int* __restrict__ mask) {
    int s = blockIdx.x * blockDim.x + threadIdx.x;
    if (s < NS_NUM) atomicAdd(&g_counts[mask[s] >> H_SHIFT], 1);
}

// single block, 256 threads: exclusive scan of 2048 counts
__global__ void scan_kernel() {
    __shared__ int chunk[256];
    int tid = threadIdx.x;
    int base = tid * 8;
    int local[8];
    int s = 0;
#pragma unroll
    for (int c = 0; c < 8; c++) { local[c] = g_counts[base + c]; s += local[c]; }
    chunk[tid] = s;
    __syncthreads();
    if (tid == 0) {
        int run = 0;
        for (int i = 0; i < 256; i++) { int t = chunk[i]; chunk[i] = run; run += t; }
        g_rowptr[H_DIM] = run;
    }
    __syncthreads();
    int run = chunk[tid];
#pragma unroll
    for (int c = 0; c < 8; c++) {
        g_rowptr[base + c]  = run;
        g_offsets[base + c] = run;
        run += local[c];
    }
}

__global__ void scatter_kernel(const int* __restrict__ mask) {
    int s = blockIdx.x * blockDim.x + threadIdx.x;
    if (s >= NS_NUM) return;
    int m = mask[s];
    int r = m >> H_SHIFT;
    int c = m & H_MASK;
    int pos = atomicAdd(&g_offsets[r], 1);
    g_colsrt[pos] = (unsigned short)c;
#pragma unroll
    for (int e = 0; e < E_NUM; e++)
        g_wsrt[e * NS_NUM + pos] = g_weighted[e * NS_NUM + s];
}

// ---------------- weighted = softmax(eaw) @ atoms * sigmoid(importance) ----------------
__global__ __launch_bounds__(256) void weighted_kernel(
    const float* __restrict__ eaw, const float* __restrict__ atoms,
    const float* __restrict__ importance)
{
    __shared__ float wsm[A_NUM];
    int e = blockIdx.y;
    int tid = threadIdx.x;
    if (tid < A_NUM) wsm[tid] = eaw[e * A_NUM + tid];
    __syncthreads();
    if (tid == 0) {
        float mx = -1e30f;
        for (int a = 0; a < A_NUM; a++) mx = fmaxf(mx, wsm[a]);
        float sm = 0.f;
        for (int a = 0; a < A_NUM; a++) { float v = expf(wsm[a] - mx); wsm[a] = v; sm += v; }
        float inv = 1.f / sm;
        for (int a = 0; a < A_NUM; a++) wsm[a] *= inv;
    }
    __syncthreads();
    int s = blockIdx.x * 256 + tid;
    float acc = 0.f;
#pragma unroll 8
    for (int a = 0; a < A_NUM; a++) acc += wsm[a] * atoms[a * NS_NUM + s];
    float imp = importance[e * NS_NUM + s];
    g_weighted[e * NS_NUM + s] = acc * (1.f / (1.f + expf(-imp)));
}

// ---------------- gating: logits, clip, top-2, softmax ----------------
__global__ __launch_bounds__(256) void gate_kernel(
    const float* __restrict__ x, const float* __restrict__ gw)
{
    __shared__ float xs[H_DIM];
    __shared__ float logits[E_NUM];
    int t = blockIdx.x;
    int tid = threadIdx.x;
    for (int i = tid; i < H_DIM; i += 256) xs[i] = x[t * H_DIM + i];
    __syncthreads();
    int w = tid >> 5, lane = tid & 31;
    const float* g = gw + w * H_DIM;
    float s = 0.f;
    for (int h = lane; h < H_DIM; h += 32) s += xs[h] * g[h];
#pragma unroll
    for (int o = 16; o; o >>= 1) s += __shfl_xor_sync(0xffffffffu, s, o);
    if (lane == 0) logits[w] = s;
    __syncthreads();
    if (tid == 0) {
        float v[E_NUM];
#pragma unroll
        for (int e = 0; e < E_NUM; e++) v[e] = fminf(50.f, fmaxf(-50.f, logits[e]));
        int i0 = 0;
#pragma unroll
        for (int e = 1; e < E_NUM; e++) if (v[e] > v[i0]) i0 = e;
        int i1 = (i0 == 0) ? 1 : 0;
#pragma unroll
        for (int e = 0; e < E_NUM; e++) if (e != i0 && v[e] > v[i1]) i1 = e;
        float d = expf(v[i1] - v[i0]);       // <= 1
        float inv = 1.f / (1.f + d);
        g_e0[t] = i0; g_e1[t] = i1;
        g_rw0[t] = inv; g_rw1[t] = d * inv;
    }
}

// ---------------- SGEMM: C = A @ B^T (A: T x K, B: N x K, row-major) ----------------
#define BM 128
#define BN 128
#define BK 16
#define SPAD 4

__global__ __launch_bounds__(256, 2) void sgemm_nt_kernel(
    const float* __restrict__ A, const float* __restrict__ B, float* __restrict__ C)
{
    __shared__ float As[BK][BM + SPAD];
    __shared__ float Bs[BK][BN + SPAD];
    const int trow0 = blockIdx.y * BM;
    const int ncol0 = blockIdx.x * BN;
    const int tid = threadIdx.x;
    const int ldRow  = tid >> 2;   // 0..63
    const int ldCol4 = tid & 3;    // 0..3 (float4 slot)
    const int tx = tid & 15;
    const int ty = tid >> 4;

    const float* Ab = A + trow0 * H_DIM;
    const float* Bb = B + ncol0 * H_DIM;

    float acc[8][8];
#pragma unroll
    for (int i = 0; i < 8; i++)
#pragma unroll
        for (int j = 0; j < 8; j++) acc[i][j] = 0.f;

    // initial tile
    {
#pragma unroll
        for (int r = 0; r < 2; r++) {
            int row = ldRow + r * 64;
            float4 va = *(const float4*)(Ab + row * H_DIM + ldCol4 * 4);
            As[ldCol4 * 4 + 0][row] = va.x;
            As[ldCol4 * 4 + 1][row] = va.y;
            As[ldCol4 * 4 + 2][row] = va.z;
            As[ldCol4 * 4 + 3][row] = va.w;
            float4 vb = *(const float4*)(Bb + row * H_DIM + ldCol4 * 4);
            Bs[ldCol4 * 4 + 0][row] = vb.x;
            Bs[ldCol4 * 4 + 1][row] = vb.y;
            Bs[ldCol4 * 4 + 2][row] = vb.z;
            Bs[ldCol4 * 4 + 3][row] = vb.w;
        }
    }
    __syncthreads();

    const int nIter = H_DIM / BK;
    for (int it = 0; it < nIter; ++it) {
        float4 pa0, pa1, pb0, pb1;
        const bool has_next = (it + 1 < nIter);
        if (has_next) {
            int k0 = (it + 1) * BK;
            pa0 = *(const float4*)(Ab + (ldRow)      * H_DIM + k0 + ldCol4 * 4);
            pa1 = *(const float4*)(Ab + (ldRow + 64) * H_DIM + k0 + ldCol4 * 4);
            pb0 = *(const float4*)(Bb + (ldRow)      * H_DIM + k0 + ldCol4 * 4);
            pb1 = *(const float4*)(Bb + (ldRow + 64) * H_DIM + k0 + ldCol4 * 4);
        }
#pragma unroll
        for (int kk = 0; kk < BK; kk++) {
            float a[8], b[8];
#pragma unroll
            for (int i = 0; i < 8; i++) a[i] = As[kk][ty * 8 + i];
#pragma unroll
            for (int j = 0; j < 8; j++) b[j] = Bs[kk][tx * 8 + j];
#pragma unroll
            for (int i = 0; i < 8; i++)
#pragma unroll
                for (int j = 0; j < 8; j++) acc[i][j] += a[i] * b[j];
        }
        __syncthreads();
        if (has_next) {
            As[ldCol4 * 4 + 0][ldRow] = pa0.x;
            As[ldCol4 * 4 + 1][ldRow] = pa0.y;
            As[ldCol4 * 4 + 2][ldRow] = pa0.z;
            As[ldCol4 * 4 + 3][ldRow] = pa0.w;
            As[ldCol4 * 4 + 0][ldRow + 64] = pa1.x;
            As[ldCol4 * 4 + 1][ldRow + 64] = pa1.y;
            As[ldCol4 * 4 + 2][ldRow + 64] = pa1.z;
            As[ldCol4 * 4 + 3][ldRow + 64] = pa1.w;
            Bs[ldCol4 * 4 + 0][ldRow] = pb0.x;
            Bs[ldCol4 * 4 + 1][ldRow] = pb0.y;
            Bs[ldCol4 * 4 + 2][ldRow] = pb0.z;
            Bs[ldCol4 * 4 + 3][ldRow] = pb0.w;
            Bs[ldCol4 * 4 + 0][ldRow + 64] = pb1.x;
            Bs[ldCol4 * 4 + 1][ldRow + 64] = pb1.y;
            Bs[ldCol4 * 4 + 2][ldRow + 64] = pb1.z;
            Bs[ldCol4 * 4 + 3][ldRow + 64] = pb1.w;
            __syncthreads();
        }
    }

#pragma unroll
    for (int i = 0; i < 8; i++) {
        int row = trow0 + ty * 8 + i;
        float* cp = C + row * H_DIM + ncol0 + tx * 8;
        float4 v0 = make_float4(acc[i][0], acc[i][1], acc[i][2], acc[i][3]);
        float4 v1 = make_float4(acc[i][4], acc[i][5], acc[i][6], acc[i][7]);
        *(float4*)cp = v0;
        *(float4*)(cp + 4) = v1;
    }
}

// ---------------- sparse contrib: out[t, r] += sum_{j in row r} xs[col_j] * comb_j ----------------
// shared: comb fp32[NS] (64KB) + xs[H] (8KB) + acc[H] (8KB) + cols u16[NS] (32KB) = 112KB
#define SPARSE_SMEM ((NS_NUM + 2 * H_DIM) * 4 + NS_NUM * 2)

__global__ __launch_bounds__(256) void sparse_kernel(
    const float* __restrict__ x, float* __restrict__ out)
{
    extern __shared__ char smraw[];
    float* comb = (float*)smraw;                      // NS_NUM
    float* xs   = comb + NS_NUM;                      // H_DIM
    float* accs = xs + H_DIM;                         // H_DIM
    unsigned short* cols = (unsigned short*)(accs + H_DIM); // NS_NUM

    int t = blockIdx.x;
    int tid = threadIdx.x;
    int e0 = g_e0[t], e1 = g_e1[t];
    float r0 = g_rw0[t], r1 = g_rw1[t];
    const float* w0 = g_wsrt + e0 * NS_NUM;
    const float* w1 = g_wsrt + e1 * NS_NUM;

    for (int i = tid; i < H_DIM; i += 256) xs[i] = x[t * H_DIM + i];
    for (int j = tid; j < NS_NUM; j += 256) {
        comb[j] = r0 * w0[j] + r1 * w1[j];
        cols[j] = g_colsrt[j];
    }
    __syncthreads();

    int base = tid * 8;                 // 8 contiguous rows per thread
    int p = g_rowptr[base];
    for (int rr = 0; rr < 8; rr++) {
        int pend = g_rowptr[base + rr + 1];
        float a = 0.f;
        for (; p < pend; p++) a += xs[cols[p]] * comb[p];
        accs[base + rr] = a;
    }
    __syncthreads();
    for (int i = tid; i < H_DIM; i += 256) out[t * H_DIM + i] += accs[i];
}

// ---------------- launch ----------------
extern "C" void kernel_launch(void* const* d_in, const int* in_sizes, int n_in,
                              void* d_out, int out_size)
{
    const float* x     = (const float*)d_in[0];  // (B,S,H) = (T,H)
    const float* gw    = (const float*)d_in[1];  // (E,H)
    const float* W     = (const float*)d_in[2];  // (H,H)
    const float* atoms = (const float*)d_in[3];  // (A,NS)
    const float* eaw   = (const float*)d_in[4];  // (E,A)
    const float* imp   = (const float*)d_in[5];  // (E,NS)
    const int*   mask  = (const int*)d_in[6];    // (NS,)
    float* out = (float*)d_out;                  // (T,H)

    (void)in_sizes; (void)n_in; (void)out_size;

    cudaFuncSetAttribute(sparse_kernel,
                         cudaFuncAttributeMaxDynamicSharedMemorySize, SPARSE_SMEM);

    // CSR build
    zero_counts_kernel<<<2, 1024>>>();
    hist_kernel<<<NS_NUM / 1024, 1024>>>(mask);
    weighted_kernel<<<dim3(NS_NUM / 256, E_NUM), 256>>>(eaw, atoms, imp);
    scan_kernel<<<1, 256>>>();
    scatter_kernel<<<NS_NUM / 1024, 1024>>>(mask);

    // gating
    gate_kernel<<<T_TOK, 256>>>(x, gw);

    // dense out = x @ W^T
    sgemm_nt_kernel<<<dim3(H_DIM / BN, T_TOK / BM), 256>>>(x, W, out);

    // sparse contrib add
    sparse_kernel<<<T_TOK, 256, SPARSE_SMEM>>>(x, out);
}

// round 4
// speedup vs baseline: 1.4815x; 1.4815x over previous
#include <cuda_runtime.h>
#include <cuda_bf16.h>
#include <math.h>

// Problem constants (fixed shapes: B=2,S=2048,H=2048,E=8,A=64,NS=16384)
#define T_TOK   4096
#define H_DIM   2048
#define E_NUM   8
#define A_NUM   64
#define NS_NUM  16384
#define H_SHIFT 11
#define H_MASK  2047

// GEMM: C[T,H] = Acat[T,KC] @ Bcat[H,KC]^T, KC = 3*H (bf16x3 split), HMMA path
#define KC      6144
#define BM      128
#define BN      128
#define BK      32
#define NCH     (KC / BK)            // 192
#define LDSB    80                   // smem row stride bytes (32 bf16 + 8 pad)
#define ATILEB  (BM * LDSB)          // 10240
#define STAGEB  ((BM + BN) * LDSB)   // 20480
#define SMEM_MMA (3 * STAGEB)        // 61440

// ---------------- device scratch (no allocations allowed) ----------------
__device__ __nv_bfloat16 g_xcat[(size_t)T_TOK * KC];   // 48MB: [xh, xh, xl]
__device__ __nv_bfloat16 g_wcat[(size_t)H_DIM * KC];   // 24MB: [Wh, Wl, Wh]
__device__ float          g_weighted[E_NUM * NS_NUM];
__device__ float          g_wsrt[E_NUM * NS_NUM];
__device__ unsigned short g_colsrt[NS_NUM];
__device__ int            g_counts[H_DIM];
__device__ int            g_rowptr[H_DIM + 1];
__device__ int            g_offsets[H_DIM];
__device__ int            g_e0[T_TOK];
__device__ int            g_e1[T_TOK];
__device__ float          g_rw0[T_TOK];
__device__ float          g_rw1[T_TOK];

// ---------------- ptx helpers (all compute_80-level, safe on compute_103) ----------------
__device__ __forceinline__ unsigned smem_u32(const void* p) {
    unsigned r;
    asm("{ .reg .u64 t; cvta.to.shared.u64 t, %1; cvt.u32.u64 %0, t; }" : "=r"(r) : "l"(p));
    return r;
}
__device__ __forceinline__ void cp16(unsigned dst, const void* src) {
    asm volatile("cp.async.cg.shared.global [%0], [%1], 16;\n" :: "r"(dst), "l"(src));
}
__device__ __forceinline__ void cp_commit() { asm volatile("cp.async.commit_group;\n" ::: "memory"); }
__device__ __forceinline__ void cp_wait1()  { asm volatile("cp.async.wait_group 1;\n" ::: "memory"); }
__device__ __forceinline__ void ldsm4(unsigned* r, unsigned addr) {
    asm volatile("ldmatrix.sync.aligned.m8n8.x4.shared.b16 {%0,%1,%2,%3}, [%4];"
                 : "=r"(r[0]), "=r"(r[1]), "=r"(r[2]), "=r"(r[3]) : "r"(addr));
}
__device__ __forceinline__ void mma16816(float* d, const unsigned* a, unsigned b0, unsigned b1) {
    asm volatile(
        "mma.sync.aligned.m16n8k16.row.col.f32.bf16.bf16.f32 "
        "{%0,%1,%2,%3}, {%4,%5,%6,%7}, {%8,%9}, {%0,%1,%2,%3};"
        : "+f"(d[0]), "+f"(d[1]), "+f"(d[2]), "+f"(d[3])
        : "r"(a[0]), "r"(a[1]), "r"(a[2]), "r"(a[3]), "r"(b0), "r"(b1));
}

// ---------------- split conversion ----------------
// xcat: cols [0,2048)=hi, [2048,4096)=hi, [4096,6144)=lo
// wcat: cols [0,2048)=hi, [2048,4096)=lo, [4096,6144)=hi
__global__ __launch_bounds__(256) void convert_kernel(
    const float* __restrict__ src, __nv_bfloat16* __restrict__ dst, int dupSecond)
{
    int idx2 = blockIdx.x * 256 + threadIdx.x;
    int row = idx2 >> 10;
    int hp  = (idx2 & 1023) << 1;
    float2 v = *(const float2*)(src + (size_t)row * H_DIM + hp);
    __nv_bfloat16 h0 = __float2bfloat16(v.x);
    __nv_bfloat16 h1 = __float2bfloat16(v.y);
    __nv_bfloat16 l0 = __float2bfloat16(v.x - __bfloat162float(h0));
    __nv_bfloat16 l1 = __float2bfloat16(v.y - __bfloat162float(h1));
    __nv_bfloat162 hi; hi.x = h0; hi.y = h1;
    __nv_bfloat162 lo; lo.x = l0; lo.y = l1;
    size_t base = (size_t)row * KC + hp;
    *(__nv_bfloat162*)(dst + base)           = hi;
    *(__nv_bfloat162*)(dst + base + H_DIM)   = dupSecond ? hi : lo;
    *(__nv_bfloat162*)(dst + base + 2*H_DIM) = dupSecond ? lo : hi;
}

// ---------------- HMMA GEMM: out = Acat @ Bcat^T ----------------
// 256 threads, 8 warps as 2(m) x 4(n); warp tile 64x32; 3-stage cp.async pipeline.
__global__ __launch_bounds__(256, 2) void mma_gemm_kernel(
    const __nv_bfloat16* __restrict__ Acat,
    const __nv_bfloat16* __restrict__ Bcat,
    float* __restrict__ out)
{
    extern __shared__ __align__(128) char sm[];
    const unsigned smb = smem_u32(sm);
    const int tid  = threadIdx.x;
    const int wid  = tid >> 5, lane = tid & 31;
    const int wm   = wid & 1;          // 0..1 (m)
    const int wn   = wid >> 1;         // 0..3 (n)
    const int trow0 = blockIdx.y * BM;
    const int ncol0 = blockIdx.x * BN;

    // cp.async plan: 4 chunks of 16B per thread per tile-half
    const int rowL = tid >> 2;         // 0..63
    const int c4   = tid & 3;          // 16B slot within 64B row segment
    const __nv_bfloat16* aSrc0 = Acat + (size_t)(trow0 + rowL) * KC + c4 * 8;
    const __nv_bfloat16* aSrc1 = Acat + (size_t)(trow0 + rowL + 64) * KC + c4 * 8;
    const __nv_bfloat16* bSrc0 = Bcat + (size_t)(ncol0 + rowL) * KC + c4 * 8;
    const __nv_bfloat16* bSrc1 = Bcat + (size_t)(ncol0 + rowL + 64) * KC + c4 * 8;
    const unsigned aDst0 = rowL * LDSB + c4 * 16;
    const unsigned aDst1 = (rowL + 64) * LDSB + c4 * 16;
    const unsigned bDst0 = ATILEB + rowL * LDSB + c4 * 16;
    const unsigned bDst1 = ATILEB + (rowL + 64) * LDSB + c4 * 16;

    // ldmatrix base addresses (non-trans x4 for both A and B)
    const unsigned lrow = lane & 15, lhalf = lane >> 4;
    const unsigned aBase = smb + (wm * 64 + lrow) * LDSB + lhalf * 16;
    const unsigned bBase = smb + ATILEB + (wn * 32 + lrow) * LDSB + lhalf * 16;

    float acc[4][4][4];
#pragma unroll
    for (int i = 0; i < 4; i++)
#pragma unroll
        for (int j = 0; j < 4; j++)
#pragma unroll
            for (int r = 0; r < 4; r++) acc[i][j][r] = 0.f;

    // prologue: stages 0,1
#pragma unroll
    for (int c = 0; c < 2; c++) {
        unsigned sb = smb + c * STAGEB;
        int k0 = c * BK;
        cp16(sb + aDst0, aSrc0 + k0); cp16(sb + aDst1, aSrc1 + k0);
        cp16(sb + bDst0, bSrc0 + k0); cp16(sb + bDst1, bSrc1 + k0);
        cp_commit();
    }

    int stage = 0;
    for (int c = 0; c < NCH; c++) {
        cp_wait1();          // stage for chunk c resident
        __syncthreads();     // visible CTA-wide; stage (c+2)%3 free (its compute done last iter)

        int m = c + 2;
        if (m < NCH) {
            int sld = m - (m / 3) * 3;
            unsigned sb = smb + sld * STAGEB;
            int k0 = m * BK;
            cp16(sb + aDst0, aSrc0 + k0); cp16(sb + aDst1, aSrc1 + k0);
            cp16(sb + bDst0, bSrc0 + k0); cp16(sb + bDst1, bSrc1 + k0);
        }
        cp_commit();

        unsigned soff = stage * STAGEB;
#pragma unroll
        for (int ks = 0; ks < 2; ks++) {
            unsigned a[4][4], b[2][4];
#pragma unroll
            for (int mi = 0; mi < 4; mi++)
                ldsm4(a[mi], aBase + soff + mi * (16 * LDSB) + ks * 32);
#pragma unroll
            for (int nj = 0; nj < 2; nj++)
                ldsm4(b[nj], bBase + soff + nj * (16 * LDSB) + ks * 32);
            // b[nj] = {r0,r1,r2,r3}: n-tile (2nj): {r0,r2}; n-tile (2nj+1): {r1,r3}
#pragma unroll
            for (int mi = 0; mi < 4; mi++) {
                mma16816(acc[mi][0], a[mi], b[0][0], b[0][2]);
                mma16816(acc[mi][1], a[mi], b[0][1], b[0][3]);
                mma16816(acc[mi][2], a[mi], b[1][0], b[1][2]);
                mma16816(acc[mi][3], a[mi], b[1][1], b[1][3]);
            }
        }
        stage++; if (stage == 3) stage = 0;
    }

    // epilogue: acc[mi][ni]: rows wm*64+mi*16+(lane>>2) and +8; cols wn*32+ni*8+(lane&3)*2
    const int r0 = trow0 + wm * 64 + (lane >> 2);
    const int cc = ncol0 + wn * 32 + (lane & 3) * 2;
#pragma unroll
    for (int mi = 0; mi < 4; mi++) {
#pragma unroll
        for (int ni = 0; ni < 4; ni++) {
            float* p0 = out + (size_t)(r0 + mi * 16) * H_DIM + cc + ni * 8;
            float* p1 = p0 + 8 * H_DIM;
            *(float2*)p0 = make_float2(acc[mi][ni][0], acc[mi][ni][1]);
            *(float2*)p1 = make_float2(acc[mi][ni][2], acc[mi][ni][3]);
        }
    }
}

// ---------------- tiny setup kernels ----------------
__global__ void zero_counts_kernel() {
    int i = blockIdx.x * blockDim.x + threadIdx.x;
    if (i < H_DIM) g_counts[i] = 0;
}
__global__ void hist_kernel(const int* __restrict__ mask) {
    int s = blockIdx.x * blockDim.x + threadIdx.x;
    if (s < NS_NUM) atomicAdd(&g_counts[mask[s] >> H_SHIFT], 1);
}
__global__ void scan_kernel() {
    __shared__ int chunk[256];
    int tid = threadIdx.x;
    int base = tid * 8;
    int local[8]; int s = 0;
#pragma unroll
    for (int c = 0; c < 8; c++) { local[c] = g_counts[base + c]; s += local[c]; }
    chunk[tid] = s;
    __syncthreads();
    if (tid == 0) {
        int run = 0;
        for (int i = 0; i < 256; i++) { int t = chunk[i]; chunk[i] = run; run += t; }
        g_rowptr[H_DIM] = run;
    }
    __syncthreads();
    int run = chunk[tid];
#pragma unroll
    for (int c = 0; c < 8; c++) {
        g_rowptr[base + c]  = run;
        g_offsets[base + c] = run;
        run += local[c];
    }
}
__global__ void scatter_kernel(const int* __restrict__ mask) {
    int s = blockIdx.x * blockDim.x + threadIdx.x;
    if (s >= NS_NUM) return;
    int m = mask[s];
    int r = m >> H_SHIFT;
    int c = m & H_MASK;
    int pos = atomicAdd(&g_offsets[r], 1);
    g_colsrt[pos] = (unsigned short)c;
#pragma unroll
    for (int e = 0; e < E_NUM; e++)
        g_wsrt[e * NS_NUM + pos] = g_weighted[e * NS_NUM + s];
}

__global__ __launch_bounds__(256) void weighted_kernel(
    const float* __restrict__ eaw, const float* __restrict__ atoms,
    const float* __restrict__ importance)
{
    __shared__ float wsm[A_NUM];
    int e = blockIdx.y;
    int tid = threadIdx.x;
    if (tid < A_NUM) wsm[tid] = eaw[e * A_NUM + tid];
    __syncthreads();
    if (tid == 0) {
        float mx = -1e30f;
        for (int a = 0; a < A_NUM; a++) mx = fmaxf(mx, wsm[a]);
        float sm = 0.f;
        for (int a = 0; a < A_NUM; a++) { float v = expf(wsm[a] - mx); wsm[a] = v; sm += v; }
        float inv = 1.f / sm;
        for (int a = 0; a < A_NUM; a++) wsm[a] *= inv;
    }
    __syncthreads();
    int s = blockIdx.x * 256 + tid;
    float acc = 0.f;
#pragma unroll 8
    for (int a = 0; a < A_NUM; a++) acc += wsm[a] * atoms[a * NS_NUM + s];
    float imp = importance[e * NS_NUM + s];
    g_weighted[e * NS_NUM + s] = acc * (1.f / (1.f + expf(-imp)));
}

__global__ __launch_bounds__(256) void gate_kernel(
    const float* __restrict__ x, const float* __restrict__ gw)
{
    __shared__ float xs[H_DIM];
    __shared__ float logits[E_NUM];
    int t = blockIdx.x;
    int tid = threadIdx.x;
    for (int i = tid; i < H_DIM; i += 256) xs[i] = x[t * H_DIM + i];
    __syncthreads();
    int w = tid >> 5, lane = tid & 31;
    const float* g = gw + w * H_DIM;
    float s = 0.f;
    for (int h = lane; h < H_DIM; h += 32) s += xs[h] * g[h];
#pragma unroll
    for (int o = 16; o; o >>= 1) s += __shfl_xor_sync(0xffffffffu, s, o);
    if (lane == 0) logits[w] = s;
    __syncthreads();
    if (tid == 0) {
        float v[E_NUM];
#pragma unroll
        for (int e = 0; e < E_NUM; e++) v[e] = fminf(50.f, fmaxf(-50.f, logits[e]));
        int i0 = 0;
#pragma unroll
        for (int e = 1; e < E_NUM; e++) if (v[e] > v[i0]) i0 = e;
        int i1 = (i0 == 0) ? 1 : 0;
#pragma unroll
        for (int e = 0; e < E_NUM; e++) if (e != i0 && v[e] > v[i1]) i1 = e;
        float d = expf(v[i1] - v[i0]);
        float inv = 1.f / (1.f + d);
        g_e0[t] = i0; g_e1[t] = i1;
        g_rw0[t] = inv; g_rw1[t] = d * inv;
    }
}

// ---------------- sparse contrib ----------------
#define SPARSE_SMEM ((NS_NUM + 2 * H_DIM) * 4 + NS_NUM * 2)

__global__ __launch_bounds__(256) void sparse_kernel(
    const float* __restrict__ x, float* __restrict__ out)
{
    extern __shared__ char smraw[];
    float* comb = (float*)smraw;
    float* xs   = comb + NS_NUM;
    float* accs = xs + H_DIM;
    unsigned short* cols = (unsigned short*)(accs + H_DIM);

    int t = blockIdx.x;
    int tid = threadIdx.x;
    int e0 = g_e0[t], e1 = g_e1[t];
    float r0 = g_rw0[t], r1 = g_rw1[t];
    const float* w0 = g_wsrt + e0 * NS_NUM;
    const float* w1 = g_wsrt + e1 * NS_NUM;

    for (int i = tid; i < H_DIM; i += 256) xs[i] = x[t * H_DIM + i];
    for (int j = tid; j < NS_NUM; j += 256) {
        comb[j] = r0 * w0[j] + r1 * w1[j];
        cols[j] = g_colsrt[j];
    }
    __syncthreads();

    int base = tid * 8;
    int p = g_rowptr[base];
    for (int rr = 0; rr < 8; rr++) {
        int pend = g_rowptr[base + rr + 1];
        float a = 0.f;
        for (; p < pend; p++) a += xs[cols[p]] * comb[p];
        accs[base + rr] = a;
    }
    __syncthreads();
    for (int i = tid; i < H_DIM; i += 256) out[t * H_DIM + i] += accs[i];
}

// ---------------- launch ----------------
extern "C" void kernel_launch(void* const* d_in, const int* in_sizes, int n_in,
                              void* d_out, int out_size)
{
    const float* x     = (const float*)d_in[0];
    const float* gw    = (const float*)d_in[1];
    const float* W     = (const float*)d_in[2];
    const float* atoms = (const float*)d_in[3];
    const float* eaw   = (const float*)d_in[4];
    const float* imp   = (const float*)d_in[5];
    const int*   mask  = (const int*)d_in[6];
    float* out = (float*)d_out;

    (void)in_sizes; (void)n_in; (void)out_size;

    void *xcat_p = nullptr, *wcat_p = nullptr;
    cudaGetSymbolAddress(&xcat_p, g_xcat);
    cudaGetSymbolAddress(&wcat_p, g_wcat);

    cudaFuncSetAttribute(sparse_kernel,
                         cudaFuncAttributeMaxDynamicSharedMemorySize, SPARSE_SMEM);
    cudaFuncSetAttribute(mma_gemm_kernel,
                         cudaFuncAttributeMaxDynamicSharedMemorySize, SMEM_MMA);

    // bf16x3 operand split
    convert_kernel<<<T_TOK * (H_DIM / 2) / 256, 256>>>(x, (__nv_bfloat16*)xcat_p, 1);
    convert_kernel<<<H_DIM * (H_DIM / 2) / 256, 256>>>(W, (__nv_bfloat16*)wcat_p, 0);

    // CSR build + expert tables
    zero_counts_kernel<<<2, 1024>>>();
    hist_kernel<<<NS_NUM / 1024, 1024>>>(mask);
    weighted_kernel<<<dim3(NS_NUM / 256, E_NUM), 256>>>(eaw, atoms, imp);
    scan_kernel<<<1, 256>>>();
    scatter_kernel<<<NS_NUM / 1024, 1024>>>(mask);

    // gating
    gate_kernel<<<T_TOK, 256>>>(x, gw);

    // dense out = x @ W^T via HMMA bf16x3
    mma_gemm_kernel<<<dim3(H_DIM / BN, T_TOK / BM), 256, SMEM_MMA>>>(
        (const __nv_bfloat16*)xcat_p, (const __nv_bfloat16*)wcat_p, out);

    // sparse contrib add
    sparse_kernel<<<T_TOK, 256, SPARSE_SMEM>>>(x, out);
}

// round 5
// speedup vs baseline: 1.8631x; 1.2576x over previous
#include <cuda_runtime.h>
#include <cuda_bf16.h>
#include <math.h>

// Problem constants (fixed shapes: B=2,S=2048,H=2048,E=8,A=64,NS=16384)
#define T_TOK   4096
#define H_DIM   2048
#define E_NUM   8
#define A_NUM   64
#define NS_NUM  16384
#define H_SHIFT 11
#define H_MASK  2047
#define PADMAX  4608
#define MAXBLK  576

// GEMM: C[T,H] = Acat[T,KC] @ Bcat[H,KC]^T, KC = 3*H (bf16x3 split), HMMA path
#define KC      6144
#define BM      128
#define BN      256
#define BK      64
#define NCH     (KC / BK)            // 96
#define LDSB    144                  // smem row stride bytes (64 bf16 + 16 pad)
#define ABYTES  (BM * LDSB)          // 18432
#define STAGEB  ((BM + BN) * LDSB)   // 55296
#define NSTG    4
#define SMEM_MMA (NSTG * STAGEB)     // 221184

// ---------------- device scratch (no allocations allowed) ----------------
__device__ __nv_bfloat16 g_xcat[(size_t)T_TOK * KC];   // 48MB: [xh, xh, xl]
__device__ __nv_bfloat16 g_wcat[(size_t)H_DIM * KC];   // 24MB: [Wh, Wl, Wh]
__device__ float          g_weighted[E_NUM * NS_NUM];
__device__ float          g_wsrt[E_NUM * NS_NUM];
__device__ unsigned short g_colsrt[NS_NUM];
__device__ int            g_counts[H_DIM];
__device__ int            g_rowptr[H_DIM + 1];
__device__ int            g_offsets[H_DIM];
__device__ int            g_e0[T_TOK];
__device__ int            g_e1[T_TOK];
__device__ float          g_rw0[T_TOK];
__device__ float          g_rw1[T_TOK];
// pair grouping
__device__ int            g_paircnt[64];
__device__ int            g_pairoff[64];
__device__ int            g_tokord[PADMAX];
__device__ int            g_blkpair[MAXBLK];
__device__ int            g_total_blocks;

// ---------------- ptx helpers (compute_80-level, safe on compute_103) ----------------
__device__ __forceinline__ unsigned smem_u32(const void* p) {
    unsigned r;
    asm("{ .reg .u64 t; cvta.to.shared.u64 t, %1; cvt.u32.u64 %0, t; }" : "=r"(r) : "l"(p));
    return r;
}
__device__ __forceinline__ void cp16(unsigned dst, const void* src) {
    asm volatile("cp.async.cg.shared.global [%0], [%1], 16;\n" :: "r"(dst), "l"(src));
}
__device__ __forceinline__ void cp_commit() { asm volatile("cp.async.commit_group;\n" ::: "memory"); }
__device__ __forceinline__ void cp_wait2()  { asm volatile("cp.async.wait_group 2;\n" ::: "memory"); }
__device__ __forceinline__ void ldsm4(unsigned* r, unsigned addr) {
    asm volatile("ldmatrix.sync.aligned.m8n8.x4.shared.b16 {%0,%1,%2,%3}, [%4];"
                 : "=r"(r[0]), "=r"(r[1]), "=r"(r[2]), "=r"(r[3]) : "r"(addr));
}
__device__ __forceinline__ void mma16816(float* d, const unsigned* a, unsigned b0, unsigned b1) {
    asm volatile(
        "mma.sync.aligned.m16n8k16.row.col.f32.bf16.bf16.f32 "
        "{%0,%1,%2,%3}, {%4,%5,%6,%7}, {%8,%9}, {%0,%1,%2,%3};"
        : "+f"(d[0]), "+f"(d[1]), "+f"(d[2]), "+f"(d[3])
        : "r"(a[0]), "r"(a[1]), "r"(a[2]), "r"(a[3]), "r"(b0), "r"(b1));
}

// ---------------- split conversion ----------------
// xcat: cols [0,2048)=hi, [2048,4096)=hi, [4096,6144)=lo
// wcat: cols [0,2048)=hi, [2048,4096)=lo, [4096,6144)=hi
__global__ __launch_bounds__(256) void convert_kernel(
    const float* __restrict__ src, __nv_bfloat16* __restrict__ dst, int dupSecond)
{
    int idx2 = blockIdx.x * 256 + threadIdx.x;
    int row = idx2 >> 10;
    int hp  = (idx2 & 1023) << 1;
    float2 v = *(const float2*)(src + (size_t)row * H_DIM + hp);
    __nv_bfloat16 h0 = __float2bfloat16(v.x);
    __nv_bfloat16 h1 = __float2bfloat16(v.y);
    __nv_bfloat16 l0 = __float2bfloat16(v.x - __bfloat162float(h0));
    __nv_bfloat16 l1 = __float2bfloat16(v.y - __bfloat162float(h1));
    __nv_bfloat162 hi; hi.x = h0; hi.y = h1;
    __nv_bfloat162 lo; lo.x = l0; lo.y = l1;
    size_t base = (size_t)row * KC + hp;
    *(__nv_bfloat162*)(dst + base)           = hi;
    *(__nv_bfloat162*)(dst + base + H_DIM)   = dupSecond ? hi : lo;
    *(__nv_bfloat162*)(dst + base + 2*H_DIM) = dupSecond ? lo : hi;
}

// ---------------- HMMA GEMM: out = Acat @ Bcat^T ----------------
// 256 threads, 8 warps as 2(m) x 4(n); warp tile 64x64; 4-stage cp.async pipeline.
__global__ __launch_bounds__(256, 1) void mma_gemm_kernel(
    const __nv_bfloat16* __restrict__ Acat,
    const __nv_bfloat16* __restrict__ Bcat,
    float* __restrict__ out)
{
    extern __shared__ __align__(128) char sm[];
    const unsigned smb = smem_u32(sm);
    const int tid  = threadIdx.x;
    const int wid  = tid >> 5, lane = tid & 31;
    const int wm   = wid & 1;          // 0..1 (m)
    const int wn   = wid >> 1;         // 0..3 (n)
    const int trow0 = blockIdx.y * BM;
    const int ncol0 = blockIdx.x * BN;

    // cp.async plan: slot = tid&7 (16B within 128B row), r0 = tid>>3 (row mod 32)
    const int slot = tid & 7;
    const int rr0  = tid >> 3;         // 0..31
    const __nv_bfloat16* aP = Acat + (size_t)(trow0 + rr0) * KC + slot * 8;
    const __nv_bfloat16* bP = Bcat + (size_t)(ncol0 + rr0) * KC + slot * 8;
    const unsigned dBase = rr0 * LDSB + slot * 16;   // A rows; B continues at ABYTES

    // ldmatrix base addresses (non-trans x4 for both A and B)
    const unsigned lrow = lane & 15, lhalf = lane >> 4;
    const unsigned aBase = smb + (wm * 64 + lrow) * LDSB + lhalf * 16;
    const unsigned bBase = smb + ABYTES + (wn * 64 + lrow) * LDSB + lhalf * 16;

    float acc[4][8][4];
#pragma unroll
    for (int i = 0; i < 4; i++)
#pragma unroll
        for (int j = 0; j < 8; j++)
#pragma unroll
            for (int r = 0; r < 4; r++) acc[i][j][r] = 0.f;

    // prologue: stages 0..2
#pragma unroll
    for (int c = 0; c < 3; c++) {
        unsigned d = smb + c * STAGEB + dBase;
        const __nv_bfloat16* ap = aP + c * BK;
        const __nv_bfloat16* bp = bP + c * BK;
#pragma unroll
        for (int i = 0; i < 4; i++) { cp16(d, ap); ap += 32 * KC; d += 32 * LDSB; }
#pragma unroll
        for (int i = 0; i < 8; i++) { cp16(d, bp); bp += 32 * KC; d += 32 * LDSB; }
        cp_commit();
    }

    for (int c = 0; c < NCH; c++) {
        cp_wait2();          // chunk c resident
        __syncthreads();

        int m = c + 3;
        if (m < NCH) {
            unsigned d = smb + (m & 3) * STAGEB + dBase;
            const __nv_bfloat16* ap = aP + m * BK;
            const __nv_bfloat16* bp = bP + m * BK;
#pragma unroll
            for (int i = 0; i < 4; i++) { cp16(d, ap); ap += 32 * KC; d += 32 * LDSB; }
#pragma unroll
            for (int i = 0; i < 8; i++) { cp16(d, bp); bp += 32 * KC; d += 32 * LDSB; }
        }
        cp_commit();

        unsigned soff = (unsigned)(c & 3) * STAGEB;
#pragma unroll
        for (int ks = 0; ks < 4; ks++) {
            unsigned a[4][4], b[4][4];
#pragma unroll
            for (int mi = 0; mi < 4; mi++)
                ldsm4(a[mi], aBase + soff + mi * (16 * LDSB) + ks * 32);
#pragma unroll
            for (int nj = 0; nj < 4; nj++)
                ldsm4(b[nj], bBase + soff + nj * (16 * LDSB) + ks * 32);
            // b[nj] = {r0,r1,r2,r3}: n-tile (2nj): {r0,r2}; n-tile (2nj+1): {r1,r3}
#pragma unroll
            for (int mi = 0; mi < 4; mi++) {
#pragma unroll
                for (int nb = 0; nb < 4; nb++) {
                    mma16816(acc[mi][2*nb],   a[mi], b[nb][0], b[nb][2]);
                    mma16816(acc[mi][2*nb+1], a[mi], b[nb][1], b[nb][3]);
                }
            }
        }
    }

    // epilogue
    const int r0 = trow0 + wm * 64 + (lane >> 2);
    const int cc = ncol0 + wn * 64 + (lane & 3) * 2;
#pragma unroll
    for (int mi = 0; mi < 4; mi++) {
#pragma unroll
        for (int ni = 0; ni < 8; ni++) {
            float* p0 = out + (size_t)(r0 + mi * 16) * H_DIM + cc + ni * 8;
            float* p1 = p0 + 8 * H_DIM;
            *(float2*)p0 = make_float2(acc[mi][ni][0], acc[mi][ni][1]);
            *(float2*)p1 = make_float2(acc[mi][ni][2], acc[mi][ni][3]);
        }
    }
}

// ---------------- tiny setup kernels ----------------
__global__ void zero_kernel() {
    int i = blockIdx.x * 1024 + threadIdx.x;
    if (i < H_DIM) g_counts[i] = 0;
    if (i < 64)    g_paircnt[i] = 0;
}
__global__ void hist_kernel(const int* __restrict__ mask) {
    int s = blockIdx.x * blockDim.x + threadIdx.x;
    if (s < NS_NUM) atomicAdd(&g_counts[mask[s] >> H_SHIFT], 1);
}
__global__ void scan_kernel() {
    __shared__ int chunk[256];
    int tid = threadIdx.x;
    int base = tid * 8;
    int local[8]; int s = 0;
#pragma unroll
    for (int c = 0; c < 8; c++) { local[c] = g_counts[base + c]; s += local[c]; }
    chunk[tid] = s;
    __syncthreads();
    if (tid == 0) {
        int run = 0;
        for (int i = 0; i < 256; i++) { int t = chunk[i]; chunk[i] = run; run += t; }
        g_rowptr[H_DIM] = run;
    }
    __syncthreads();
    int run = chunk[tid];
#pragma unroll
    for (int c = 0; c < 8; c++) {
        g_rowptr[base + c]  = run;
        g_offsets[base + c] = run;
        run += local[c];
    }
}
__global__ void scatter_kernel(const int* __restrict__ mask) {
    int s = blockIdx.x * blockDim.x + threadIdx.x;
    if (s >= NS_NUM) return;
    int m = mask[s];
    int r = m >> H_SHIFT;
    int c = m & H_MASK;
    int pos = atomicAdd(&g_offsets[r], 1);
    g_colsrt[pos] = (unsigned short)c;
#pragma unroll
    for (int e = 0; e < E_NUM; e++)
        g_wsrt[e * NS_NUM + pos] = g_weighted[e * NS_NUM + s];
}

// pair grouping: padded exclusive scan over the 64 (e0,e1) pair counts
__global__ void pair_scan_kernel() {
    __shared__ int ptr[65];
    int tid = threadIdx.x;
    if (tid == 0) {
        int run = 0;
        for (int k = 0; k < 64; k++) {
            ptr[k] = run;
            run += ((g_paircnt[k] + 7) >> 3) << 3;
        }
        ptr[64] = run;
        g_total_blocks = run >> 3;
    }
    __syncthreads();
    for (int i = tid; i < 64; i += 256) g_pairoff[i] = ptr[i];
    for (int i = tid; i < PADMAX; i += 256) g_tokord[i] = -1;
    for (int k = tid; k < 64; k += 256) {
        int b0 = ptr[k] >> 3, b1 = ptr[k + 1] >> 3;
        for (int b = b0; b < b1; b++) g_blkpair[b] = k;
    }
}
__global__ void pair_scatter_kernel() {
    int t = blockIdx.x * blockDim.x + threadIdx.x;
    if (t >= T_TOK) return;
    int key = g_e0[t] * 8 + g_e1[t];
    int pos = atomicAdd(&g_pairoff[key], 1);
    g_tokord[pos] = t;
}

__global__ __launch_bounds__(256) void weighted_kernel(
    const float* __restrict__ eaw, const float* __restrict__ atoms,
    const float* __restrict__ importance)
{
    __shared__ float wsm[A_NUM];
    int e = blockIdx.y;
    int tid = threadIdx.x;
    if (tid < A_NUM) wsm[tid] = eaw[e * A_NUM + tid];
    __syncthreads();
    if (tid == 0) {
        float mx = -1e30f;
        for (int a = 0; a < A_NUM; a++) mx = fmaxf(mx, wsm[a]);
        float sm = 0.f;
        for (int a = 0; a < A_NUM; a++) { float v = expf(wsm[a] - mx); wsm[a] = v; sm += v; }
        float inv = 1.f / sm;
        for (int a = 0; a < A_NUM; a++) wsm[a] *= inv;
    }
    __syncthreads();
    int s = blockIdx.x * 256 + tid;
    float acc = 0.f;
#pragma unroll 8
    for (int a = 0; a < A_NUM; a++) acc += wsm[a] * atoms[a * NS_NUM + s];
    float imp = importance[e * NS_NUM + s];
    g_weighted[e * NS_NUM + s] = acc * (1.f / (1.f + expf(-imp)));
}

__global__ __launch_bounds__(256) void gate_kernel(
    const float* __restrict__ x, const float* __restrict__ gw)
{
    __shared__ float xs[H_DIM];
    __shared__ float logits[E_NUM];
    int t = blockIdx.x;
    int tid = threadIdx.x;
    for (int i = tid; i < H_DIM; i += 256) xs[i] = x[t * H_DIM + i];
    __syncthreads();
    int w = tid >> 5, lane = tid & 31;
    const float* g = gw + w * H_DIM;
    float s = 0.f;
    for (int h = lane; h < H_DIM; h += 32) s += xs[h] * g[h];
#pragma unroll
    for (int o = 16; o; o >>= 1) s += __shfl_xor_sync(0xffffffffu, s, o);
    if (lane == 0) logits[w] = s;
    __syncthreads();
    if (tid == 0) {
        float v[E_NUM];
#pragma unroll
        for (int e = 0; e < E_NUM; e++) v[e] = fminf(50.f, fmaxf(-50.f, logits[e]));
        int i0 = 0;
#pragma unroll
        for (int e = 1; e < E_NUM; e++) if (v[e] > v[i0]) i0 = e;
        int i1 = (i0 == 0) ? 1 : 0;
#pragma unroll
        for (int e = 0; e < E_NUM; e++) if (e != i0 && v[e] > v[i1]) i1 = e;
        float d = expf(v[i1] - v[i0]);
        float inv = 1.f / (1.f + d);
        g_e0[t] = i0; g_e1[t] = i1;
        g_rw0[t] = inv; g_rw1[t] = d * inv;
        atomicAdd(&g_paircnt[i0 * 8 + i1], 1);
    }
}

// ---------------- sparse contrib, pair-grouped: 8 tokens per block ----------------
// smem: w0 64KB | w1 64KB | xs2[2048][8] 64KB | cols u16 32KB | rws 16f | toks 8i
#define SP2_W0   0
#define SP2_W1   (NS_NUM * 4)
#define SP2_XS   (2 * NS_NUM * 4)
#define SP2_COL  (SP2_XS + H_DIM * 8 * 4)
#define SP2_RWS  (SP2_COL + NS_NUM * 2)
#define SP2_SMEM (SP2_RWS + 128)

__global__ __launch_bounds__(256, 1) void sparse2_kernel(
    const float* __restrict__ x, float* __restrict__ out)
{
    extern __shared__ char sm2[];
    float* w0s = (float*)(sm2 + SP2_W0);
    float* w1s = (float*)(sm2 + SP2_W1);
    float* xs2 = (float*)(sm2 + SP2_XS);
    unsigned short* cols = (unsigned short*)(sm2 + SP2_COL);
    float* rws = (float*)(sm2 + SP2_RWS);       // r0[8], r1[8]
    int*   tks = (int*)(rws + 16);

    int b = blockIdx.x;
    if (b >= g_total_blocks) return;
    int pair = g_blkpair[b];
    const float* w0 = g_wsrt + (pair >> 3) * NS_NUM;
    const float* w1 = g_wsrt + (pair & 7) * NS_NUM;
    int tid = threadIdx.x;

    if (tid < 8) {
        int tok = g_tokord[b * 8 + tid];
        tks[tid] = tok;
        rws[tid]     = tok >= 0 ? g_rw0[tok] : 0.f;
        rws[8 + tid] = tok >= 0 ? g_rw1[tok] : 0.f;
    }
    for (int j = tid; j < NS_NUM; j += 256) {
        w0s[j] = w0[j];
        w1s[j] = w1[j];
        cols[j] = g_colsrt[j];
    }
    __syncthreads();

    int tk[8]; float r0v[8], r1v[8];
#pragma unroll
    for (int t = 0; t < 8; t++) { tk[t] = tks[t]; r0v[t] = rws[t]; r1v[t] = rws[8 + t]; }

    // stage x rows transposed: xs2[i*8 + t]
#pragma unroll 1
    for (int t = 0; t < 8; t++) {
        if (tk[t] >= 0) {
            const float* xp = x + (size_t)tk[t] * H_DIM;
            for (int i = tid; i < H_DIM; i += 256) xs2[i * 8 + t] = xp[i];
        } else {
            for (int i = tid; i < H_DIM; i += 256) xs2[i * 8 + t] = 0.f;
        }
    }
    __syncthreads();

    float acc[8][8];
#pragma unroll
    for (int rr = 0; rr < 8; rr++)
#pragma unroll
        for (int t = 0; t < 8; t++) acc[rr][t] = 0.f;

#pragma unroll 1
    for (int rr = 0; rr < 8; rr++) {
        int row = tid + rr * 256;              // adjacent lanes -> adjacent rows
        int p    = g_rowptr[row];
        int pend = g_rowptr[row + 1];
        for (; p < pend; p++) {
            int cidx = cols[p];
            float w0p = w0s[p], w1p = w1s[p];
            float4 xa = *(float4*)(xs2 + cidx * 8);
            float4 xb = *(float4*)(xs2 + cidx * 8 + 4);
            acc[rr][0] += xa.x * (r0v[0] * w0p + r1v[0] * w1p);
            acc[rr][1] += xa.y * (r0v[1] * w0p + r1v[1] * w1p);
            acc[rr][2] += xa.z * (r0v[2] * w0p + r1v[2] * w1p);
            acc[rr][3] += xa.w * (r0v[3] * w0p + r1v[3] * w1p);
            acc[rr][4] += xb.x * (r0v[4] * w0p + r1v[4] * w1p);
            acc[rr][5] += xb.y * (r0v[5] * w0p + r1v[5] * w1p);
            acc[rr][6] += xb.z * (r0v[6] * w0p + r1v[6] * w1p);
            acc[rr][7] += xb.w * (r0v[7] * w0p + r1v[7] * w1p);
        }
    }

#pragma unroll 1
    for (int t = 0; t < 8; t++) {
        if (tk[t] < 0) continue;
        float* op = out + (size_t)tk[t] * H_DIM;
#pragma unroll
        for (int rr = 0; rr < 8; rr++) {
            int row = tid + rr * 256;
            op[row] += acc[rr][t];
        }
    }
}

// ---------------- launch ----------------
extern "C" void kernel_launch(void* const* d_in, const int* in_sizes, int n_in,
                              void* d_out, int out_size)
{
    const float* x     = (const float*)d_in[0];
    const float* gw    = (const float*)d_in[1];
    const float* W     = (const float*)d_in[2];
    const float* atoms = (const float*)d_in[3];
    const float* eaw   = (const float*)d_in[4];
    const float* imp   = (const float*)d_in[5];
    const int*   mask  = (const int*)d_in[6];
    float* out = (float*)d_out;

    (void)in_sizes; (void)n_in; (void)out_size;

    void *xcat_p = nullptr, *wcat_p = nullptr;
    cudaGetSymbolAddress(&xcat_p, g_xcat);
    cudaGetSymbolAddress(&wcat_p, g_wcat);

    cudaFuncSetAttribute(mma_gemm_kernel,
                         cudaFuncAttributeMaxDynamicSharedMemorySize, SMEM_MMA);
    cudaFuncSetAttribute(sparse2_kernel,
                         cudaFuncAttributeMaxDynamicSharedMemorySize, SP2_SMEM);

    // 1,2: bf16x3 operand split
    convert_kernel<<<T_TOK * (H_DIM / 2) / 256, 256>>>(x, (__nv_bfloat16*)xcat_p, 1);
    convert_kernel<<<H_DIM * (H_DIM / 2) / 256, 256>>>(W, (__nv_bfloat16*)wcat_p, 0);
    // 3
    zero_kernel<<<2, 1024>>>();
    // 4: dense out = x @ W^T via HMMA bf16x3 (profiled launch)
    mma_gemm_kernel<<<dim3(H_DIM / BN, T_TOK / BM), 256, SMEM_MMA>>>(
        (const __nv_bfloat16*)xcat_p, (const __nv_bfloat16*)wcat_p, out);
    // 5-7
    hist_kernel<<<NS_NUM / 1024, 1024>>>(mask);
    weighted_kernel<<<dim3(NS_NUM / 256, E_NUM), 256>>>(eaw, atoms, imp);
    gate_kernel<<<T_TOK, 256>>>(x, gw);
    // 8-11: CSR + pair grouping
    scan_kernel<<<1, 256>>>();
    pair_scan_kernel<<<1, 256>>>();
    pair_scatter_kernel<<<T_TOK / 256, 256>>>();
    scatter_kernel<<<NS_NUM / 1024, 1024>>>(mask);
    // 12: sparse contrib add
    sparse2_kernel<<<MAXBLK, 256, SP2_SMEM>>>(x, out);
}